// round 5
// baseline (speedup 1.0000x reference)
#include <cuda_runtime.h>
#include <math.h>

#define TT   200
#define BB   1024
#define DD   128
#define TOBS 140
#define LL   20
#define LATD 32
#define GU   200
#define UNI  100
#define GIN  168      /* effective K: y(40)+x(128); ones-row folded into colsum */
#define ROWS 8
#define NTHR 768
#define NBLK (BB / ROWS)

#define KS3  56       /* K per split for GRU l1 (3 splits) */

#define SM_FLOATS 55552

__device__ float g_colsum[3 * GU];

__global__ void colsum_kernel(const float* __restrict__ uw1,
                              const float* __restrict__ rw1,
                              const float* __restrict__ nw1) {
    int j = threadIdx.x;
    const float* w = (blockIdx.x == 0) ? uw1 : (blockIdx.x == 1 ? rw1 : nw1);
    float sacc = 0.f;
    for (int k = GIN; k < 2 * LL + 2 * DD; ++k) sacc += w[k * GU + j];
    g_colsum[blockIdx.x * GU + j] = sacc;
}

// ---- GRU layer1 dual (u,r): K-split 3, tiles of 4 with prefetch ----
__device__ __forceinline__ void gru_l1_dual_ks(const float* __restrict__ wA,
                                               const float* __restrict__ wB,
                                               const float* __restrict__ ycT,
                                               float* __restrict__ pL1,
                                               int j, int ks) {
    float aA[8], aB[8];
#pragma unroll
    for (int r = 0; r < 8; ++r) { aA[r] = 0.f; aB[r] = 0.f; }
    const float* pA = wA + (size_t)ks * KS3 * GU + j;
    const float* pB = wB + (size_t)ks * KS3 * GU + j;
    const float* yc = ycT + ks * KS3 * 8;
    float wa[4], wb[4];
#pragma unroll
    for (int kk = 0; kk < 4; ++kk) { wa[kk] = pA[kk * GU]; wb[kk] = pB[kk * GU]; }
#pragma unroll 1
    for (int t = 0; t < 14; ++t) {
        float na[4], nb[4];
        if (t + 1 < 14) {
#pragma unroll
            for (int kk = 0; kk < 4; ++kk) {
                na[kk] = pA[((t + 1) * 4 + kk) * GU];
                nb[kk] = pB[((t + 1) * 4 + kk) * GU];
            }
        }
#pragma unroll
        for (int kk = 0; kk < 4; ++kk) {
            int k = t * 4 + kk;
            float4 y0 = *(const float4*)(yc + k * 8);
            float4 y1 = *(const float4*)(yc + k * 8 + 4);
            float w0 = wa[kk], w1 = wb[kk];
            aA[0] += y0.x * w0; aA[1] += y0.y * w0; aA[2] += y0.z * w0; aA[3] += y0.w * w0;
            aA[4] += y1.x * w0; aA[5] += y1.y * w0; aA[6] += y1.z * w0; aA[7] += y1.w * w0;
            aB[0] += y0.x * w1; aB[1] += y0.y * w1; aB[2] += y0.z * w1; aB[3] += y0.w * w1;
            aB[4] += y1.x * w1; aB[5] += y1.y * w1; aB[6] += y1.z * w1; aB[7] += y1.w * w1;
        }
#pragma unroll
        for (int kk = 0; kk < 4; ++kk) { wa[kk] = na[kk]; wb[kk] = nb[kk]; }
    }
    float* u = pL1 + ks * 1600 + j * 8;           // [g=0][ks][j][r]
    float* rr = pL1 + 4800 + ks * 1600 + j * 8;   // [g=1][ks][j][r]
    *(float4*)u        = make_float4(aA[0], aA[1], aA[2], aA[3]);
    *(float4*)(u + 4)  = make_float4(aA[4], aA[5], aA[6], aA[7]);
    *(float4*)rr       = make_float4(aB[0], aB[1], aB[2], aB[3]);
    *(float4*)(rr + 4) = make_float4(aB[4], aB[5], aB[6], aB[7]);
}

// ---- GRU n layer1: K-split 3, ks0 scales first 40 k by rT inline ----
__device__ __forceinline__ void gru_l1_n_ks(const float* __restrict__ wA,
                                            const float* __restrict__ ycT,
                                            const float* __restrict__ rT,
                                            float* __restrict__ pL1,
                                            int j, int ks) {
    float aA[8];
#pragma unroll
    for (int r = 0; r < 8; ++r) aA[r] = 0.f;
    const float* pA = wA + (size_t)ks * KS3 * GU + j;
    const float* yc = ycT + ks * KS3 * 8;
    const int nscale = (ks == 0) ? 10 : 0;   // tiles of 4: k<40 -> tiles 0..9
    float wa[4];
#pragma unroll
    for (int kk = 0; kk < 4; ++kk) wa[kk] = pA[kk * GU];
#pragma unroll 1
    for (int t = 0; t < 14; ++t) {
        float na[4];
        if (t + 1 < 14) {
#pragma unroll
            for (int kk = 0; kk < 4; ++kk) na[kk] = pA[((t + 1) * 4 + kk) * GU];
        }
        if (t < nscale) {
#pragma unroll
            for (int kk = 0; kk < 4; ++kk) {
                int k = t * 4 + kk;
                float4 y0 = *(const float4*)(yc + k * 8);
                float4 y1 = *(const float4*)(yc + k * 8 + 4);
                float4 r0 = *(const float4*)(rT + k * 8);
                float4 r1 = *(const float4*)(rT + k * 8 + 4);
                y0.x *= r0.x; y0.y *= r0.y; y0.z *= r0.z; y0.w *= r0.w;
                y1.x *= r1.x; y1.y *= r1.y; y1.z *= r1.z; y1.w *= r1.w;
                float w0 = wa[kk];
                aA[0] += y0.x * w0; aA[1] += y0.y * w0; aA[2] += y0.z * w0; aA[3] += y0.w * w0;
                aA[4] += y1.x * w0; aA[5] += y1.y * w0; aA[6] += y1.z * w0; aA[7] += y1.w * w0;
            }
        } else {
#pragma unroll
            for (int kk = 0; kk < 4; ++kk) {
                int k = t * 4 + kk;
                float4 y0 = *(const float4*)(yc + k * 8);
                float4 y1 = *(const float4*)(yc + k * 8 + 4);
                float w0 = wa[kk];
                aA[0] += y0.x * w0; aA[1] += y0.y * w0; aA[2] += y0.z * w0; aA[3] += y0.w * w0;
                aA[4] += y1.x * w0; aA[5] += y1.y * w0; aA[6] += y1.z * w0; aA[7] += y1.w * w0;
            }
        }
#pragma unroll
        for (int kk = 0; kk < 4; ++kk) wa[kk] = na[kk];
    }
    float* p = pL1 + ks * 1600 + j * 8;
    *(float4*)p       = make_float4(aA[0], aA[1], aA[2], aA[3]);
    *(float4*)(p + 4) = make_float4(aA[4], aA[5], aA[6], aA[7]);
}

// encoder MLP: l1 direct (400 thr, 2 rows), l2 partials (200 thr)
__device__ __forceinline__ void enc_eval(const float* __restrict__ ew1,
                                         const float* __restrict__ eb1,
                                         const float* __restrict__ ew2,
                                         const float* __restrict__ ytmpT,
                                         float* __restrict__ hencT,
                                         float* __restrict__ pe, int tid) {
    if (tid < 400) {
        int j = tid % UNI, rq = tid / UNI;   // rows 2rq, 2rq+1
        float a0 = eb1[j], a1 = a0;
#pragma unroll
        for (int k = 0; k < LL; ++k) {
            float w = ew1[k * UNI + j];
            float2 yv = *(const float2*)(ytmpT + k * 8 + 2 * rq);
            a0 += yv.x * w; a1 += yv.y * w;
        }
        *(float2*)(hencT + j * 8 + 2 * rq) = make_float2(tanhf(a0), tanhf(a1));
    }
    __syncthreads();
    if (tid < 200) {
        int jj = tid % LL, ks = tid / LL;   // ks 0..9, K=10
        float a[8];
#pragma unroll
        for (int r = 0; r < 8; ++r) a[r] = 0.f;
#pragma unroll
        for (int k = ks * 10; k < ks * 10 + 10; ++k) {
            float w = ew2[k * LL + jj];
            float4 y0 = *(const float4*)(hencT + k * 8);
            float4 y1 = *(const float4*)(hencT + k * 8 + 4);
            a[0] += y0.x * w; a[1] += y0.y * w; a[2] += y0.z * w; a[3] += y0.w * w;
            a[4] += y1.x * w; a[5] += y1.y * w; a[6] += y1.z * w; a[7] += y1.w * w;
        }
        float* p = pe + ks * 160 + jj * 8;
        *(float4*)p       = make_float4(a[0], a[1], a[2], a[3]);
        *(float4*)(p + 4) = make_float4(a[4], a[5], a[6], a[7]);
    }
    __syncthreads();
}

#define ENC_K(tidv) (pe[(tidv)] + pe[160 + (tidv)] + pe[320 + (tidv)] + pe[480 + (tidv)] + \
                     pe[640 + (tidv)] + pe[800 + (tidv)] + pe[960 + (tidv)] + pe[1120 + (tidv)] + \
                     pe[1280 + (tidv)] + pe[1440 + (tidv)] + eb2[(tidv) >> 3])

// decoder MLP: zin [32][8] -> pd3 partials [10][32][8]
__device__ __forceinline__ void dec_eval(const float* __restrict__ dw1,
                                         const float* __restrict__ db1,
                                         const float* __restrict__ dw2,
                                         const float* __restrict__ db2,
                                         const float* __restrict__ dw3,
                                         const float* __restrict__ zin,
                                         float* __restrict__ h1T,
                                         float* __restrict__ h2T,
                                         float* __restrict__ pd2,
                                         float* __restrict__ pd3, int tid) {
    // l1: direct, 400 thr, 2 rows each, K=32
    if (tid < 400) {
        int j = tid % UNI, rq = tid / UNI;
        float a0 = db1[j], a1 = a0;
#pragma unroll 8
        for (int k = 0; k < LATD; ++k) {
            float w = dw1[k * UNI + j];
            float2 zv = *(const float2*)(zin + k * 8 + 2 * rq);
            a0 += zv.x * w; a1 += zv.y * w;
        }
        *(float2*)(h1T + j * 8 + 2 * rq) = make_float2(tanhf(a0), tanhf(a1));
    }
    __syncthreads();
    // l2: 600 thr: j x ks3 x rh2, 4 rows, K={34,33,33}
    if (tid < 600) {
        int j = tid % UNI, q = tid / UNI;       // q 0..5
        int ks = q % 3, rh = q / 3;
        int k0 = (ks == 0) ? 0 : (ks == 1 ? 34 : 67);
        int k1 = (ks == 0) ? 34 : (ks == 1 ? 67 : 100);
        float a[4];
#pragma unroll
        for (int r = 0; r < 4; ++r) a[r] = 0.f;
#pragma unroll 4
        for (int k = k0; k < k1; ++k) {
            float w = dw2[k * UNI + j];
            float4 z0 = *(const float4*)(h1T + k * 8 + 4 * rh);
            a[0] += z0.x * w; a[1] += z0.y * w; a[2] += z0.z * w; a[3] += z0.w * w;
        }
        *(float4*)(pd2 + ks * 800 + j * 8 + 4 * rh) = make_float4(a[0], a[1], a[2], a[3]);
    }
    __syncthreads();
    for (int i = tid; i < 800; i += NTHR)
        h2T[i] = tanhf(pd2[i] + pd2[800 + i] + pd2[1600 + i] + db2[i >> 3]);
    __syncthreads();
    // l3: 640 thr: j32 x ks10 x rh2, 4 rows, K=10
    if (tid < 640) {
        int j = tid % LATD, q = tid / LATD;     // q 0..19
        int ks = q % 10, rh = q / 10;
        float a[4];
#pragma unroll
        for (int r = 0; r < 4; ++r) a[r] = 0.f;
#pragma unroll
        for (int k = ks * 10; k < ks * 10 + 10; ++k) {
            float w = dw3[k * LATD + j];
            float4 z0 = *(const float4*)(h2T + k * 8 + 4 * rh);
            a[0] += z0.x * w; a[1] += z0.y * w; a[2] += z0.z * w; a[3] += z0.w * w;
        }
        *(float4*)(pd3 + ks * 256 + j * 8 + 4 * rh) = make_float4(a[0], a[1], a[2], a[3]);
    }
    __syncthreads();
}

#define DEC_K(tidv) (pd3[(tidv)] + pd3[256 + (tidv)] + pd3[512 + (tidv)] + pd3[768 + (tidv)] + \
                     pd3[1024 + (tidv)] + pd3[1280 + (tidv)] + pd3[1536 + (tidv)] + pd3[1792 + (tidv)] + \
                     pd3[2048 + (tidv)] + pd3[2304 + (tidv)] + db3[(tidv) >> 3])

extern "C" __global__ void __launch_bounds__(NTHR, 1)
latent_ode_main(const float* __restrict__ truth, const float* __restrict__ tarr,
                const int* __restrict__ obs_idx, const float* __restrict__ eps,
                const float* __restrict__ ew1g, const float* __restrict__ eb1g,
                const float* __restrict__ ew2g, const float* __restrict__ eb2g,
                const float* __restrict__ uw1, const float* __restrict__ ub1g,
                const float* __restrict__ uw2g, const float* __restrict__ ub2g,
                const float* __restrict__ rw1, const float* __restrict__ rb1g,
                const float* __restrict__ rw2g, const float* __restrict__ rb2g,
                const float* __restrict__ nw1, const float* __restrict__ nb1g,
                const float* __restrict__ nw2g, const float* __restrict__ nb2g,
                const float* __restrict__ z0w1, const float* __restrict__ z0b1,
                const float* __restrict__ z0w2, const float* __restrict__ z0b2,
                const float* __restrict__ dw1g, const float* __restrict__ db1g,
                const float* __restrict__ dw2g, const float* __restrict__ db2g,
                const float* __restrict__ dw3g, const float* __restrict__ db3g,
                const float* __restrict__ owg, const float* __restrict__ obg,
                float* __restrict__ out) {
    extern __shared__ float s[];
    const int tid = threadIdx.x;
    const int b0 = blockIdx.x * ROWS;

    float* zT = s;           // [32][8] k-major, persistent
    float* P  = s + 256;

    // ---------------- encoder smem layout ----------------
    float* ew1   = P;            // 2000
    float* ew2   = P + 2000;     // 2000
    float* eb1   = P + 4000;     // 100
    float* eb2   = P + 4100;     // 20 (pad to 4128)
    float* uw2   = P + 4128;     // 8000
    float* rw2   = P + 12128;    // 8000
    float* nw2   = P + 20128;    // 8000
    float* ub1   = P + 28128;    // 200
    float* rb1   = P + 28328;    // 200
    float* nb1   = P + 28528;    // 200
    float* ub2   = P + 28728;    // 40
    float* rb2   = P + 28768;    // 40
    float* nb2   = P + 28808;    // 40
    float* csu   = P + 28848;    // 200
    float* csr   = P + 29048;    // 200
    float* csn   = P + 29248;    // 200
    float* y     = P + 29448;    // 320  [8][40]
    float* ycT   = P + 29768;    // 1344 [168][8]
    float* ytmpT = P + 31112;    // 160
    float* accT  = P + 31272;    // 160
    float* hencT = P + 31432;    // 800
    float* pe    = P + 32232;    // 1600 [10][20][8]
    float* hTa   = P + 33832;    // 1600 [200][8]
    float* hTb   = P + 35432;    // 1600
    float* pL1   = P + 37032;    // 9600 [2g][3ks][200][8]
    float* p2    = P + 46632;    // 5120 [2g][8ks][40][8]
    float* pn    = P + 51752;    // 2560 [8ks][40][8]
    float* u_    = P + 54312;    // 320  [8][40]
    float* rT    = P + 54632;    // 320  [40][8]
    float* dts   = P + 54952;    // 140  encoder step dt
    float* ddt   = P + 55092;    // 200  decoder step dt (persists; outside decoder alias)

    for (int i = tid; i < 2000; i += NTHR) { ew1[i] = ew1g[i]; ew2[i] = ew2g[i]; }
    for (int i = tid; i < 100;  i += NTHR) eb1[i] = eb1g[i];
    for (int i = tid; i < 20;   i += NTHR) eb2[i] = eb2g[i];
    for (int i = tid; i < 8000; i += NTHR) { uw2[i] = uw2g[i]; rw2[i] = rw2g[i]; nw2[i] = nw2g[i]; }
    for (int i = tid; i < 200;  i += NTHR) {
        ub1[i] = ub1g[i]; rb1[i] = rb1g[i]; nb1[i] = nb1g[i];
        csu[i] = g_colsum[i]; csr[i] = g_colsum[200 + i]; csn[i] = g_colsum[400 + i];
    }
    for (int i = tid; i < 40; i += NTHR) { ub2[i] = ub2g[i]; rb2[i] = rb2g[i]; nb2[i] = nb2g[i]; }
    for (int i = tid; i < ROWS * 40; i += NTHR) y[i] = 0.f;
    for (int i = tid; i < TOBS; i += NTHR) {
        dts[i] = (i > 0) ? (tarr[obs_idx[TOBS - 1 - i]] - tarr[obs_idx[TOBS - i]]) : 0.f;
    }
    for (int i = tid; i < TT - 1; i += NTHR) ddt[i] = tarr[i + 1] - tarr[i];
    __syncthreads();

    // ================= encoder scan =================
    for (int st = 0; st < TOBS; ++st) {
        int io = obs_idx[TOBS - 1 - st];
        float dt = dts[st];

        // ---- RK4 on ym ----
        if (tid < 160) { int j = tid >> 3, r = tid & 7; ytmpT[tid] = y[r * 40 + j]; }
        __syncthreads();
        enc_eval(ew1, eb1, ew2, ytmpT, hencT, pe, tid);
        if (tid < 160) {
            int j = tid >> 3, r = tid & 7;
            float kv = ENC_K(tid);
            accT[tid] = kv;
            ytmpT[tid] = y[r * 40 + j] + 0.5f * dt * kv;
        }
        __syncthreads();
        enc_eval(ew1, eb1, ew2, ytmpT, hencT, pe, tid);
        if (tid < 160) {
            int j = tid >> 3, r = tid & 7;
            float kv = ENC_K(tid);
            accT[tid] += 2.f * kv;
            ytmpT[tid] = y[r * 40 + j] + 0.5f * dt * kv;
        }
        __syncthreads();
        enc_eval(ew1, eb1, ew2, ytmpT, hencT, pe, tid);
        if (tid < 160) {
            int j = tid >> 3, r = tid & 7;
            float kv = ENC_K(tid);
            accT[tid] += 2.f * kv;
            ytmpT[tid] = y[r * 40 + j] + dt * kv;
        }
        __syncthreads();
        enc_eval(ew1, eb1, ew2, ytmpT, hencT, pe, tid);
        if (tid < 160) {
            int j = tid >> 3, r = tid & 7;
            float kv = ENC_K(tid);
            y[r * 40 + j] += dt * (1.f / 6.f) * (accT[tid] + kv);
        }
        __syncthreads();

        // ---- build ycT (coalesced truth reads) ----
        for (int i = tid; i < GIN * ROWS; i += NTHR) {
            int r = i / GIN, k = i % GIN;
            float v = (k < 40) ? y[r * 40 + k]
                               : truth[(size_t)io * (BB * DD) + (size_t)(b0 + r) * DD + (k - 40)];
            ycT[k * 8 + r] = v;
        }
        __syncthreads();

        // ---- u,r layer1 (K-split 3, 600 thr) ----
        if (tid < 600)
            gru_l1_dual_ks(uw1, rw1, ycT, pL1, tid % GU, tid / GU);
        __syncthreads();
        for (int i = tid; i < 3200; i += NTHR) {
            int g = i / 1600, rem = i % 1600, j = rem >> 3;
            float base = g ? (csr[j] + rb1[j]) : (csu[j] + ub1[j]);
            const float* p = pL1 + g * 4800;
            (g ? hTb : hTa)[rem] = tanhf(p[rem] + p[1600 + rem] + p[3200 + rem] + base);
        }
        __syncthreads();

        // ---- u,r layer2 (640 thr: g2 x j40 x ks8, K=25) ----
        if (tid < 640) {
            int g = tid / 320, rem = tid % 320, jj = rem % 40, ks = rem / 40;
            const float* hT = g ? hTb : hTa;
            const float* w2 = g ? rw2 : uw2;
            float a[8];
#pragma unroll
            for (int r = 0; r < 8; ++r) a[r] = 0.f;
#pragma unroll 5
            for (int k = ks * 25; k < ks * 25 + 25; ++k) {
                float w = w2[k * 40 + jj];
                float4 h0 = *(const float4*)(hT + k * 8);
                float4 h1 = *(const float4*)(hT + k * 8 + 4);
                a[0] += h0.x * w; a[1] += h0.y * w; a[2] += h0.z * w; a[3] += h0.w * w;
                a[4] += h1.x * w; a[5] += h1.y * w; a[6] += h1.z * w; a[7] += h1.w * w;
            }
            float* p = p2 + g * 2560 + ks * 320 + jj * 8;
            *(float4*)p       = make_float4(a[0], a[1], a[2], a[3]);
            *(float4*)(p + 4) = make_float4(a[4], a[5], a[6], a[7]);
        }
        __syncthreads();
        // reduce + sigmoid: u -> row-major u_, r -> k-major rT
        if (tid < 640) {
            int g = tid / 320, rem = tid % 320, jj = rem >> 3, r = rem & 7;
            const float* p = p2 + g * 2560;
            float a = p[rem] + p[320 + rem] + p[640 + rem] + p[960 + rem]
                    + p[1280 + rem] + p[1600 + rem] + p[1920 + rem] + p[2240 + rem]
                    + (g ? rb2 : ub2)[jj];
            float sg = 1.f / (1.f + expf(-a));
            if (g) rT[jj * 8 + r] = sg; else u_[r * 40 + jj] = sg;
        }
        __syncthreads();

        // ---- n layer1 (K-split 3, 600 thr; ks0 scales y-part by rT inline) ----
        if (tid < 600)
            gru_l1_n_ks(nw1, ycT, rT, pL1, tid % GU, tid / GU);
        __syncthreads();
        for (int i = tid; i < 1600; i += NTHR) {
            int j = i >> 3;
            hTa[i] = tanhf(pL1[i] + pL1[1600 + i] + pL1[3200 + i] + csn[j] + nb1[j]);
        }
        __syncthreads();

        // ---- n layer2 (640 thr: j40 x ks8 x rh2, K=25, 4 rows) ----
        if (tid < 640) {
            int jj = tid % 40, q = tid / 40;    // q 0..15
            int ks = q % 8, rh = q / 8;
            float a[4];
#pragma unroll
            for (int r = 0; r < 4; ++r) a[r] = 0.f;
#pragma unroll 5
            for (int k = ks * 25; k < ks * 25 + 25; ++k) {
                float w = nw2[k * 40 + jj];
                float4 h0 = *(const float4*)(hTa + k * 8 + 4 * rh);
                a[0] += h0.x * w; a[1] += h0.y * w; a[2] += h0.z * w; a[3] += h0.w * w;
            }
            *(float4*)(pn + ks * 320 + jj * 8 + 4 * rh) = make_float4(a[0], a[1], a[2], a[3]);
        }
        __syncthreads();
        // reduce + state update
        if (tid < 320) {
            int jj = tid >> 3, r = tid & 7;
            float a = pn[tid] + pn[320 + tid] + pn[640 + tid] + pn[960 + tid]
                    + pn[1280 + tid] + pn[1600 + tid] + pn[1920 + tid] + pn[2240 + tid] + nb2[jj];
            float val = (jj < LL) ? a : fabsf(a);
            float uu = u_[r * 40 + jj];
            y[r * 40 + jj] = (1.f - uu) * val + uu * y[r * 40 + jj];
        }
        __syncthreads();
    }

    // ================= z0 head (once) =================
    for (int i = tid; i < ROWS * UNI; i += NTHR) {
        int r = i / UNI, j = i % UNI;
        float a = z0b1[j];
#pragma unroll 4
        for (int k = 0; k < 40; ++k) a += y[r * 40 + k] * z0w1[k * UNI + j];
        hencT[i] = tanhf(a);
    }
    __syncthreads();
    for (int i = tid; i < ROWS * 64; i += NTHR) {
        int r = i / 64, j = i % 64;
        float a = z0b2[j];
#pragma unroll 4
        for (int k = 0; k < UNI; ++k) a += hencT[r * UNI + k] * z0w2[k * 64 + j];
        hTa[r * 64 + j] = a;
    }
    __syncthreads();
    if (tid < 256) {
        int r = tid >> 5, j = tid & 31;
        float m = hTa[r * 64 + j];
        float sd = fabsf(hTa[r * 64 + 32 + j]);
        zT[j * 8 + r] = m + eps[(size_t)(b0 + r) * LATD + j] * sd;
    }
    __syncthreads();

    // ---------------- decoder smem layout (aliases P; ddt preserved) ----------------
    float* dw1   = P;             // 3200
    float* dw2   = P + 3200;      // 10000
    float* dw3   = P + 13200;     // 3200
    float* db1   = P + 16400;     // 100
    float* db2   = P + 16500;     // 100
    float* db3   = P + 16600;     // 32
    float* ow    = P + 16632;     // 4096
    float* ob    = P + 20728;     // 128
    float* h1T   = P + 20856;     // 800
    float* h2T   = P + 21656;     // 800
    float* ztmpT = P + 22456;     // 256
    float* zacc  = P + 22712;     // 256
    float* pd2   = P + 22968;     // 2400 [3][100][8]
    float* pd3   = P + 25368;     // 2560 [10][32][8]
    float* pp    = P + 27928;     // 3072 [3][128][8]

    for (int i = tid; i < 3200;  i += NTHR) { dw1[i] = dw1g[i]; dw3[i] = dw3g[i]; }
    for (int i = tid; i < 10000; i += NTHR) dw2[i] = dw2g[i];
    for (int i = tid; i < 100;   i += NTHR) { db1[i] = db1g[i]; db2[i] = db2g[i]; }
    for (int i = tid; i < 32;    i += NTHR) db3[i] = db3g[i];
    for (int i = tid; i < 4096;  i += NTHR) ow[i] = owg[i];
    for (int i = tid; i < 128;   i += NTHR) ob[i] = obg[i];
    __syncthreads();

    // projection helper macro-ish via lambda-free code (t=0 and each step)
    for (int ti = 0; ti < TT; ++ti) {
        if (ti > 0) {
            float dt = ddt[ti - 1];
            if (tid < 256) ztmpT[tid] = zT[tid];
            __syncthreads();
            dec_eval(dw1, db1, dw2, db2, dw3, ztmpT, h1T, h2T, pd2, pd3, tid);
            if (tid < 256) {
                float kv = DEC_K(tid);
                zacc[tid] = kv;
                ztmpT[tid] = zT[tid] + 0.5f * dt * kv;
            }
            __syncthreads();
            dec_eval(dw1, db1, dw2, db2, dw3, ztmpT, h1T, h2T, pd2, pd3, tid);
            if (tid < 256) {
                float kv = DEC_K(tid);
                zacc[tid] += 2.f * kv;
                ztmpT[tid] = zT[tid] + 0.5f * dt * kv;
            }
            __syncthreads();
            dec_eval(dw1, db1, dw2, db2, dw3, ztmpT, h1T, h2T, pd2, pd3, tid);
            if (tid < 256) {
                float kv = DEC_K(tid);
                zacc[tid] += 2.f * kv;
                ztmpT[tid] = zT[tid] + dt * kv;
            }
            __syncthreads();
            dec_eval(dw1, db1, dw2, db2, dw3, ztmpT, h1T, h2T, pd2, pd3, tid);
            if (tid < 256) {
                float kv = DEC_K(tid);
                zT[tid] += dt * (1.f / 6.f) * (zacc[tid] + kv);
            }
            __syncthreads();
        }

        // output projection: 768 thr (d128 x h3 x rh2, K={11,11,10}, 4 rows)
        {
            int d = tid % DD, q = tid / DD;     // q 0..5
            int h = q % 3, rh = q / 3;
            int k0 = (h == 0) ? 0 : (h == 1 ? 11 : 22);
            int k1 = (h == 0) ? 11 : (h == 1 ? 22 : 32);
            float a[4];
#pragma unroll
            for (int r = 0; r < 4; ++r) a[r] = 0.f;
#pragma unroll 4
            for (int k = k0; k < k1; ++k) {
                float w = ow[k * DD + d];
                float4 z0 = *(const float4*)(zT + k * 8 + 4 * rh);
                a[0] += z0.x * w; a[1] += z0.y * w; a[2] += z0.z * w; a[3] += z0.w * w;
            }
            *(float4*)(pp + h * 1024 + d * 8 + 4 * rh) = make_float4(a[0], a[1], a[2], a[3]);
        }
        __syncthreads();
        if (tid < DD) {
            int d = tid;
#pragma unroll
            for (int r = 0; r < 8; ++r)
                out[(size_t)(b0 + r) * (TT * DD) + (size_t)ti * DD + d] =
                    pp[d * 8 + r] + pp[1024 + d * 8 + r] + pp[2048 + d * 8 + r] + ob[d];
        }
        __syncthreads();
    }
}

extern "C" void kernel_launch(void* const* d_in, const int* in_sizes, int n_in,
                              void* d_out, int out_size) {
    (void)in_sizes; (void)n_in; (void)out_size;
    size_t smem = (size_t)SM_FLOATS * sizeof(float);
    cudaFuncSetAttribute(latent_ode_main, cudaFuncAttributeMaxDynamicSharedMemorySize, (int)smem);

    colsum_kernel<<<3, GU>>>((const float*)d_in[8], (const float*)d_in[12], (const float*)d_in[16]);

    latent_ode_main<<<NBLK, NTHR, smem>>>(
        (const float*)d_in[0], (const float*)d_in[1], (const int*)d_in[2], (const float*)d_in[3],
        (const float*)d_in[4],  (const float*)d_in[5],  (const float*)d_in[6],  (const float*)d_in[7],
        (const float*)d_in[8],  (const float*)d_in[9],  (const float*)d_in[10], (const float*)d_in[11],
        (const float*)d_in[12], (const float*)d_in[13], (const float*)d_in[14], (const float*)d_in[15],
        (const float*)d_in[16], (const float*)d_in[17], (const float*)d_in[18], (const float*)d_in[19],
        (const float*)d_in[20], (const float*)d_in[21], (const float*)d_in[22], (const float*)d_in[23],
        (const float*)d_in[24], (const float*)d_in[25], (const float*)d_in[26], (const float*)d_in[27],
        (const float*)d_in[28], (const float*)d_in[29], (const float*)d_in[30], (const float*)d_in[31],
        (float*)d_out);
}

// round 6
// speedup vs baseline: 1.0441x; 1.0441x over previous
#include <cuda_runtime.h>
#include <math.h>

#define TT   200
#define BB   1024
#define DD   128
#define TOBS 140
#define LL   20
#define LATD 32
#define GU   200
#define UNI  100
#define GIN  168      /* effective K: y(40)+x(128); ones-row folded into colsum */
#define ROWS 8
#define NTHR 512
#define NBLK (BB / ROWS)

#define KH   84       /* K per half for GRU l1 split-2 */

#define SM_FLOATS 51208

__device__ float g_colsum[3 * GU];

__global__ void colsum_kernel(const float* __restrict__ uw1,
                              const float* __restrict__ rw1,
                              const float* __restrict__ nw1) {
    int j = threadIdx.x;
    const float* w = (blockIdx.x == 0) ? uw1 : (blockIdx.x == 1 ? rw1 : nw1);
    float sacc = 0.f;
    for (int k = GIN; k < 2 * LL + 2 * DD; ++k) sacc += w[k * GU + j];
    g_colsum[blockIdx.x * GU + j] = sacc;
}

// ---- GRU layer1, dual gate (u,r), K-split half, pipelined weight prefetch ----
__device__ __forceinline__ void gru_l1_dual_ks(const float* __restrict__ wA,
                                               const float* __restrict__ wB,
                                               const float* __restrict__ ycT,
                                               float* __restrict__ pU,
                                               float* __restrict__ pR,
                                               int j, int ks) {
    float aA[8], aB[8];
#pragma unroll
    for (int r = 0; r < 8; ++r) { aA[r] = 0.f; aB[r] = 0.f; }
    const float* pA = wA + (size_t)ks * KH * GU + j;
    const float* pB = wB + (size_t)ks * KH * GU + j;
    const float* yc = ycT + ks * KH * 8;
    float wa[6], wb[6];
#pragma unroll
    for (int kk = 0; kk < 6; ++kk) { wa[kk] = pA[kk * GU]; wb[kk] = pB[kk * GU]; }
#pragma unroll 1
    for (int t = 0; t < 14; ++t) {
        float na[6], nb[6];
        if (t + 1 < 14) {
#pragma unroll
            for (int kk = 0; kk < 6; ++kk) {
                na[kk] = pA[((t + 1) * 6 + kk) * GU];
                nb[kk] = pB[((t + 1) * 6 + kk) * GU];
            }
        }
#pragma unroll
        for (int kk = 0; kk < 6; ++kk) {
            int k = t * 6 + kk;
            float4 y0 = *(const float4*)(yc + k * 8);
            float4 y1 = *(const float4*)(yc + k * 8 + 4);
            float w0 = wa[kk], w1 = wb[kk];
            aA[0] += y0.x * w0; aA[1] += y0.y * w0; aA[2] += y0.z * w0; aA[3] += y0.w * w0;
            aA[4] += y1.x * w0; aA[5] += y1.y * w0; aA[6] += y1.z * w0; aA[7] += y1.w * w0;
            aB[0] += y0.x * w1; aB[1] += y0.y * w1; aB[2] += y0.z * w1; aB[3] += y0.w * w1;
            aB[4] += y1.x * w1; aB[5] += y1.y * w1; aB[6] += y1.z * w1; aB[7] += y1.w * w1;
        }
        if (t + 1 < 14) {
#pragma unroll
            for (int kk = 0; kk < 6; ++kk) { wa[kk] = na[kk]; wb[kk] = nb[kk]; }
        }
    }
    float* u = pU + ks * 1600 + j * 8;
    float* rr = pR + ks * 1600 + j * 8;
    *(float4*)u        = make_float4(aA[0], aA[1], aA[2], aA[3]);
    *(float4*)(u + 4)  = make_float4(aA[4], aA[5], aA[6], aA[7]);
    *(float4*)rr       = make_float4(aB[0], aB[1], aB[2], aB[3]);
    *(float4*)(rr + 4) = make_float4(aB[4], aB[5], aB[6], aB[7]);
}

__device__ __forceinline__ void gru_l1_single_ks(const float* __restrict__ wA,
                                                 const float* __restrict__ ycT,
                                                 float* __restrict__ pN,
                                                 int j, int ks) {
    float aA[8];
#pragma unroll
    for (int r = 0; r < 8; ++r) aA[r] = 0.f;
    const float* pA = wA + (size_t)ks * KH * GU + j;
    const float* yc = ycT + ks * KH * 8;
    float wa[12];
#pragma unroll
    for (int kk = 0; kk < 12; ++kk) wa[kk] = pA[kk * GU];
#pragma unroll 1
    for (int t = 0; t < 7; ++t) {
        float na[12];
        if (t + 1 < 7) {
#pragma unroll
            for (int kk = 0; kk < 12; ++kk) na[kk] = pA[((t + 1) * 12 + kk) * GU];
        }
#pragma unroll
        for (int kk = 0; kk < 12; ++kk) {
            int k = t * 12 + kk;
            float4 y0 = *(const float4*)(yc + k * 8);
            float4 y1 = *(const float4*)(yc + k * 8 + 4);
            float w0 = wa[kk];
            aA[0] += y0.x * w0; aA[1] += y0.y * w0; aA[2] += y0.z * w0; aA[3] += y0.w * w0;
            aA[4] += y1.x * w0; aA[5] += y1.y * w0; aA[6] += y1.z * w0; aA[7] += y1.w * w0;
        }
        if (t + 1 < 7) {
#pragma unroll
            for (int kk = 0; kk < 12; ++kk) wa[kk] = na[kk];
        }
    }
    float* p = pN + ks * 1600 + j * 8;
    *(float4*)p       = make_float4(aA[0], aA[1], aA[2], aA[3]);
    *(float4*)(p + 4) = make_float4(aA[4], aA[5], aA[6], aA[7]);
}

// encoder MLP: l1 direct (400 thr, 2 rows, no reduce), l2 partials (200 thr)
__device__ __forceinline__ void enc_eval(const float* __restrict__ ew1,
                                         const float* __restrict__ eb1,
                                         const float* __restrict__ ew2,
                                         const float* __restrict__ ytmpT,
                                         float* __restrict__ hencT,
                                         float* __restrict__ pe, int tid) {
    if (tid < 400) {
        int j = tid % UNI, rq = tid / UNI;   // rows 2rq, 2rq+1
        float a0 = eb1[j], a1 = a0;
#pragma unroll
        for (int k = 0; k < LL; ++k) {
            float w = ew1[k * UNI + j];
            float2 yv = *(const float2*)(ytmpT + k * 8 + 2 * rq);
            a0 += yv.x * w; a1 += yv.y * w;
        }
        *(float2*)(hencT + j * 8 + 2 * rq) = make_float2(tanhf(a0), tanhf(a1));
    }
    __syncthreads();
    if (tid < 200) {
        int jj = tid % LL, ks = tid / LL;   // ks 0..9, K=10
        float a[8];
#pragma unroll
        for (int r = 0; r < 8; ++r) a[r] = 0.f;
#pragma unroll
        for (int k = ks * 10; k < ks * 10 + 10; ++k) {
            float w = ew2[k * LL + jj];
            float4 y0 = *(const float4*)(hencT + k * 8);
            float4 y1 = *(const float4*)(hencT + k * 8 + 4);
            a[0] += y0.x * w; a[1] += y0.y * w; a[2] += y0.z * w; a[3] += y0.w * w;
            a[4] += y1.x * w; a[5] += y1.y * w; a[6] += y1.z * w; a[7] += y1.w * w;
        }
        float* p = pe + ks * 160 + jj * 8;
        *(float4*)p       = make_float4(a[0], a[1], a[2], a[3]);
        *(float4*)(p + 4) = make_float4(a[4], a[5], a[6], a[7]);
    }
    __syncthreads();
}

#define ENC_K(tidv) (pe[(tidv)] + pe[160 + (tidv)] + pe[320 + (tidv)] + pe[480 + (tidv)] + \
                     pe[640 + (tidv)] + pe[800 + (tidv)] + pe[960 + (tidv)] + pe[1120 + (tidv)] + \
                     pe[1280 + (tidv)] + pe[1440 + (tidv)] + eb2[(tidv) >> 3])

// decoder MLP: l1 direct; l2 K-split 4 (8-row); l3 K-split 10 (8-row)
__device__ __forceinline__ void dec_eval(const float* __restrict__ dw1,
                                         const float* __restrict__ db1,
                                         const float* __restrict__ dw2,
                                         const float* __restrict__ db2,
                                         const float* __restrict__ dw3,
                                         const float* __restrict__ zin,
                                         float* __restrict__ h1T,
                                         float* __restrict__ h2T,
                                         float* __restrict__ pd2,
                                         float* __restrict__ pd3, int tid) {
    if (tid < 400) {
        int j = tid % UNI, rq = tid / UNI;
        float a0 = db1[j], a1 = a0;
#pragma unroll 8
        for (int k = 0; k < LATD; ++k) {
            float w = dw1[k * UNI + j];
            float2 zv = *(const float2*)(zin + k * 8 + 2 * rq);
            a0 += zv.x * w; a1 += zv.y * w;
        }
        *(float2*)(h1T + j * 8 + 2 * rq) = make_float2(tanhf(a0), tanhf(a1));
    }
    __syncthreads();
    if (tid < 400) {
        int j = tid % UNI, ks = tid / UNI;   // ks 0..3, K=25
        float a[8];
#pragma unroll
        for (int r = 0; r < 8; ++r) a[r] = 0.f;
#pragma unroll 5
        for (int k = ks * 25; k < ks * 25 + 25; ++k) {
            float w = dw2[k * UNI + j];
            float4 z0 = *(const float4*)(h1T + k * 8);
            float4 z1 = *(const float4*)(h1T + k * 8 + 4);
            a[0] += z0.x * w; a[1] += z0.y * w; a[2] += z0.z * w; a[3] += z0.w * w;
            a[4] += z1.x * w; a[5] += z1.y * w; a[6] += z1.z * w; a[7] += z1.w * w;
        }
        float* p = pd2 + ks * 800 + j * 8;
        *(float4*)p       = make_float4(a[0], a[1], a[2], a[3]);
        *(float4*)(p + 4) = make_float4(a[4], a[5], a[6], a[7]);
    }
    __syncthreads();
    for (int i = tid; i < 800; i += NTHR)
        h2T[i] = tanhf(pd2[i] + pd2[800 + i] + pd2[1600 + i] + pd2[2400 + i] + db2[i >> 3]);
    __syncthreads();
    if (tid < 320) {
        int jj = tid % LATD, ks = tid / LATD;  // ks 0..9, K=10
        float a[8];
#pragma unroll
        for (int r = 0; r < 8; ++r) a[r] = 0.f;
#pragma unroll
        for (int k = ks * 10; k < ks * 10 + 10; ++k) {
            float w = dw3[k * LATD + jj];
            float4 z0 = *(const float4*)(h2T + k * 8);
            float4 z1 = *(const float4*)(h2T + k * 8 + 4);
            a[0] += z0.x * w; a[1] += z0.y * w; a[2] += z0.z * w; a[3] += z0.w * w;
            a[4] += z1.x * w; a[5] += z1.y * w; a[6] += z1.z * w; a[7] += z1.w * w;
        }
        float* p = pd3 + ks * 256 + jj * 8;
        *(float4*)p       = make_float4(a[0], a[1], a[2], a[3]);
        *(float4*)(p + 4) = make_float4(a[4], a[5], a[6], a[7]);
    }
    __syncthreads();
}

#define DEC_K(tidv) (pd3[(tidv)] + pd3[256 + (tidv)] + pd3[512 + (tidv)] + pd3[768 + (tidv)] + \
                     pd3[1024 + (tidv)] + pd3[1280 + (tidv)] + pd3[1536 + (tidv)] + pd3[1792 + (tidv)] + \
                     pd3[2048 + (tidv)] + pd3[2304 + (tidv)] + db3[(tidv) >> 3])

extern "C" __global__ void __launch_bounds__(NTHR, 1)
latent_ode_main(const float* __restrict__ truth, const float* __restrict__ tarr,
                const int* __restrict__ obs_idx, const float* __restrict__ eps,
                const float* __restrict__ ew1g, const float* __restrict__ eb1g,
                const float* __restrict__ ew2g, const float* __restrict__ eb2g,
                const float* __restrict__ uw1, const float* __restrict__ ub1g,
                const float* __restrict__ uw2g, const float* __restrict__ ub2g,
                const float* __restrict__ rw1, const float* __restrict__ rb1g,
                const float* __restrict__ rw2g, const float* __restrict__ rb2g,
                const float* __restrict__ nw1, const float* __restrict__ nb1g,
                const float* __restrict__ nw2g, const float* __restrict__ nb2g,
                const float* __restrict__ z0w1, const float* __restrict__ z0b1,
                const float* __restrict__ z0w2, const float* __restrict__ z0b2,
                const float* __restrict__ dw1g, const float* __restrict__ db1g,
                const float* __restrict__ dw2g, const float* __restrict__ db2g,
                const float* __restrict__ dw3g, const float* __restrict__ db3g,
                const float* __restrict__ owg, const float* __restrict__ obg,
                float* __restrict__ out) {
    extern __shared__ float s[];
    const int tid = threadIdx.x;
    const int b0 = blockIdx.x * ROWS;

    float* zT = s;           // [32][8] k-major, persistent
    float* P  = s + 256;

    // ---------------- encoder smem layout ----------------
    float* ew1   = P;            // 2000
    float* ew2   = P + 2000;     // 2000
    float* eb1   = P + 4000;     // 100
    float* eb2   = P + 4100;     // 20 (pad to 4128)
    float* uw2   = P + 4128;     // 8000
    float* rw2   = P + 12128;    // 8000
    float* nw2   = P + 20128;    // 8000
    float* ub1   = P + 28128;    // 200
    float* rb1   = P + 28328;    // 200
    float* nb1   = P + 28528;    // 200
    float* ub2   = P + 28728;    // 40
    float* rb2   = P + 28768;    // 40
    float* nb2   = P + 28808;    // 40
    float* csu   = P + 28848;    // 200
    float* csr   = P + 29048;    // 200
    float* csn   = P + 29248;    // 200
    float* y     = P + 29448;    // 320  [8][40]
    float* ycT   = P + 29768;    // 1344 [168][8]
    float* ytmpT = P + 31112;    // 160
    float* accT  = P + 31272;    // 160
    float* hencT = P + 31432;    // 800
    float* pe    = P + 33832;    // 1600 [10][20][8]  (gap 32232-33832 unused)
    float* hTa   = P + 35432;    // 1600 [200][8]
    float* hTb   = P + 37032;    // 1600
    float* pL1   = P + 38632;    // 6400 [2 gates][2 ks][200][8]
    float* p2    = P + 45032;    // 2560 [2][4][40][8]
    float* pn    = P + 47592;    // 2560 [8][40][8]
    float* u_    = P + 50152;    // 320  [8][40]
    float* dts   = P + 50472;    // 140
    float* iob   = P + 50612;    // 140 (ints as bits)
    float* ddt   = P + 50752;    // 200 (outside decoder alias region -> persists)

    for (int i = tid; i < 2000; i += NTHR) { ew1[i] = ew1g[i]; ew2[i] = ew2g[i]; }
    for (int i = tid; i < 100;  i += NTHR) eb1[i] = eb1g[i];
    for (int i = tid; i < 20;   i += NTHR) eb2[i] = eb2g[i];
    for (int i = tid; i < 8000; i += NTHR) { uw2[i] = uw2g[i]; rw2[i] = rw2g[i]; nw2[i] = nw2g[i]; }
    for (int i = tid; i < 200;  i += NTHR) {
        ub1[i] = ub1g[i]; rb1[i] = rb1g[i]; nb1[i] = nb1g[i];
        csu[i] = g_colsum[i]; csr[i] = g_colsum[200 + i]; csn[i] = g_colsum[400 + i];
    }
    for (int i = tid; i < 40; i += NTHR) { ub2[i] = ub2g[i]; rb2[i] = rb2g[i]; nb2[i] = nb2g[i]; }
    for (int i = tid; i < ROWS * 40; i += NTHR) y[i] = 0.f;
    for (int i = tid; i < TOBS; i += NTHR) {
        int io = obs_idx[TOBS - 1 - i];
        iob[i] = __int_as_float(io);
        dts[i] = (i > 0) ? (tarr[io] - tarr[obs_idx[TOBS - i]]) : 0.f;
    }
    for (int i = tid; i < TT - 1; i += NTHR) ddt[i] = tarr[i + 1] - tarr[i];
    __syncthreads();

    // ================= encoder scan =================
    for (int st = 0; st < TOBS; ++st) {
        int io = __float_as_int(iob[st]);
        float dt = dts[st];

        // ---- RK4 on ym ----
        if (tid < 160) { int j = tid >> 3, r = tid & 7; ytmpT[tid] = y[r * 40 + j]; }
        __syncthreads();
        enc_eval(ew1, eb1, ew2, ytmpT, hencT, pe, tid);
        if (tid < 160) {
            int j = tid >> 3, r = tid & 7;
            float kv = ENC_K(tid);
            accT[tid] = kv;
            ytmpT[tid] = y[r * 40 + j] + 0.5f * dt * kv;
        }
        __syncthreads();
        enc_eval(ew1, eb1, ew2, ytmpT, hencT, pe, tid);
        if (tid < 160) {
            int j = tid >> 3, r = tid & 7;
            float kv = ENC_K(tid);
            accT[tid] += 2.f * kv;
            ytmpT[tid] = y[r * 40 + j] + 0.5f * dt * kv;
        }
        __syncthreads();
        enc_eval(ew1, eb1, ew2, ytmpT, hencT, pe, tid);
        if (tid < 160) {
            int j = tid >> 3, r = tid & 7;
            float kv = ENC_K(tid);
            accT[tid] += 2.f * kv;
            ytmpT[tid] = y[r * 40 + j] + dt * kv;
        }
        __syncthreads();
        enc_eval(ew1, eb1, ew2, ytmpT, hencT, pe, tid);
        if (tid < 160) {
            int j = tid >> 3, r = tid & 7;
            float kv = ENC_K(tid);
            y[r * 40 + j] += dt * (1.f / 6.f) * (accT[tid] + kv);
        }
        __syncthreads();

        // ---- build ycT ----
        for (int i = tid; i < GIN * ROWS; i += NTHR) {
            int k = i >> 3, r = i & 7;
            ycT[i] = (k < 40) ? y[r * 40 + k]
                              : truth[(size_t)io * (BB * DD) + (size_t)(b0 + r) * DD + (k - 40)];
        }
        __syncthreads();

        // ---- u,r layer1 (K-split 2, 400 thr) ----
        if (tid < 400)
            gru_l1_dual_ks(uw1, rw1, ycT, pL1, pL1 + 3200, tid % GU, tid / GU);
        __syncthreads();
        // reduce + bias + tanh
        for (int i = tid; i < 3200; i += NTHR) {
            int g = i / 1600, rem = i % 1600, j = rem >> 3;
            float base = g ? (csr[j] + rb1[j]) : (csu[j] + ub1[j]);
            float v = pL1[g * 3200 + rem] + pL1[g * 3200 + 1600 + rem] + base;
            (g ? hTb : hTa)[rem] = tanhf(v);
        }
        __syncthreads();

        // ---- u,r layer2 (K-split 4, 320 thr) ----
        if (tid < 320) {
            int g = tid / 160, rem = tid % 160, jj = rem % 40, ks = rem / 40;  // K=50
            const float* hT = g ? hTb : hTa;
            const float* w2 = g ? rw2 : uw2;
            float a[8];
#pragma unroll
            for (int r = 0; r < 8; ++r) a[r] = 0.f;
#pragma unroll 10
            for (int k = ks * 50; k < ks * 50 + 50; ++k) {
                float w = w2[k * 40 + jj];
                float4 h0 = *(const float4*)(hT + k * 8);
                float4 h1 = *(const float4*)(hT + k * 8 + 4);
                a[0] += h0.x * w; a[1] += h0.y * w; a[2] += h0.z * w; a[3] += h0.w * w;
                a[4] += h1.x * w; a[5] += h1.y * w; a[6] += h1.z * w; a[7] += h1.w * w;
            }
            float* p = p2 + g * 1280 + ks * 320 + jj * 8;
            *(float4*)p       = make_float4(a[0], a[1], a[2], a[3]);
            *(float4*)(p + 4) = make_float4(a[4], a[5], a[6], a[7]);
        }
        __syncthreads();
        // reduce + sigmoid; g==1 (r gate) scales ycT in place, g==0 stores u_
        for (int i = tid; i < 640; i += NTHR) {
            int g = i / 320, rem = i % 320, jj = rem >> 3, r = rem & 7;
            const float* p = p2 + g * 1280;
            float a = p[rem] + p[320 + rem] + p[640 + rem] + p[960 + rem] + (g ? rb2 : ub2)[jj];
            float sg = 1.f / (1.f + expf(-a));
            if (g) ycT[jj * 8 + r] *= sg;   // rem == jj*8+r, jj<40: y-part of ycT
            else   u_[r * 40 + jj] = sg;
        }
        __syncthreads();

        // ---- n layer1 (K-split 2, 400 thr; ycT already r-scaled) ----
        if (tid < 400)
            gru_l1_single_ks(nw1, ycT, pL1, tid % GU, tid / GU);
        __syncthreads();
        for (int i = tid; i < 1600; i += NTHR) {
            int j = i >> 3;
            hTa[i] = tanhf(pL1[i] + pL1[1600 + i] + csn[j] + nb1[j]);
        }
        __syncthreads();

        // ---- n layer2 (K-split 8, 320 thr) ----
        if (tid < 320) {
            int jj = tid % 40, ks = tid / 40;   // K=25
            float a[8];
#pragma unroll
            for (int r = 0; r < 8; ++r) a[r] = 0.f;
#pragma unroll 5
            for (int k = ks * 25; k < ks * 25 + 25; ++k) {
                float w = nw2[k * 40 + jj];
                float4 h0 = *(const float4*)(hTa + k * 8);
                float4 h1 = *(const float4*)(hTa + k * 8 + 4);
                a[0] += h0.x * w; a[1] += h0.y * w; a[2] += h0.z * w; a[3] += h0.w * w;
                a[4] += h1.x * w; a[5] += h1.y * w; a[6] += h1.z * w; a[7] += h1.w * w;
            }
            float* p = pn + ks * 320 + jj * 8;
            *(float4*)p       = make_float4(a[0], a[1], a[2], a[3]);
            *(float4*)(p + 4) = make_float4(a[4], a[5], a[6], a[7]);
        }
        __syncthreads();
        // reduce + state update
        if (tid < 320) {
            int jj = tid >> 3, r = tid & 7;
            float a = pn[tid] + pn[320 + tid] + pn[640 + tid] + pn[960 + tid]
                    + pn[1280 + tid] + pn[1600 + tid] + pn[1920 + tid] + pn[2240 + tid] + nb2[jj];
            float val = (jj < LL) ? a : fabsf(a);
            float uu = u_[r * 40 + jj];
            y[r * 40 + jj] = (1.f - uu) * val + uu * y[r * 40 + jj];
        }
        __syncthreads();
    }

    // ================= z0 head (once) =================
    for (int i = tid; i < ROWS * UNI; i += NTHR) {
        int r = i / UNI, j = i % UNI;
        float a = z0b1[j];
#pragma unroll 4
        for (int k = 0; k < 40; ++k) a += y[r * 40 + k] * z0w1[k * UNI + j];
        hencT[i] = tanhf(a);
    }
    __syncthreads();
    for (int i = tid; i < ROWS * 64; i += NTHR) {
        int r = i / 64, j = i % 64;
        float a = z0b2[j];
#pragma unroll 4
        for (int k = 0; k < UNI; ++k) a += hencT[r * UNI + k] * z0w2[k * 64 + j];
        hTa[r * 64 + j] = a;
    }
    __syncthreads();
    if (tid < 256) {
        int r = tid >> 5, j = tid & 31;
        float m = hTa[r * 64 + j];
        float sd = fabsf(hTa[r * 64 + 32 + j]);
        zT[j * 8 + r] = m + eps[(size_t)(b0 + r) * LATD + j] * sd;
    }
    __syncthreads();

    // ---------------- decoder smem layout (aliases P; ddt beyond -> safe) ----------------
    float* dw1   = P;             // 3200
    float* dw2   = P + 3200;      // 10000
    float* dw3   = P + 13200;     // 3200
    float* db1   = P + 16400;     // 100
    float* db2   = P + 16500;     // 100
    float* db3   = P + 16600;     // 32
    float* ow    = P + 16632;     // 4096
    float* ob    = P + 20728;     // 128
    float* h1T   = P + 20856;     // 800
    float* h2T   = P + 21656;     // 800
    float* ztmpT = P + 22456;     // 256
    float* zacc  = P + 22712;     // 256
    float* pd2   = P + 22968;     // 3200 [4][100][8]
    float* pd3   = P + 26168;     // 2560 [10][32][8]
    float* pp    = P + 28728;     // 2048 [2][128][8]

    for (int i = tid; i < 3200;  i += NTHR) { dw1[i] = dw1g[i]; dw3[i] = dw3g[i]; }
    for (int i = tid; i < 10000; i += NTHR) dw2[i] = dw2g[i];
    for (int i = tid; i < 100;   i += NTHR) { db1[i] = db1g[i]; db2[i] = db2g[i]; }
    for (int i = tid; i < 32;    i += NTHR) db3[i] = db3g[i];
    for (int i = tid; i < 4096;  i += NTHR) ow[i] = owg[i];
    for (int i = tid; i < 128;   i += NTHR) ob[i] = obg[i];
    __syncthreads();

    // ================= decoder scan + projection =================
    for (int ti = 0; ti < TT; ++ti) {
        if (ti > 0) {
            float dt = ddt[ti - 1];
            if (tid < 256) ztmpT[tid] = zT[tid];
            __syncthreads();
            dec_eval(dw1, db1, dw2, db2, dw3, ztmpT, h1T, h2T, pd2, pd3, tid);
            if (tid < 256) {
                float kv = DEC_K(tid);
                zacc[tid] = kv;
                ztmpT[tid] = zT[tid] + 0.5f * dt * kv;
            }
            __syncthreads();
            dec_eval(dw1, db1, dw2, db2, dw3, ztmpT, h1T, h2T, pd2, pd3, tid);
            if (tid < 256) {
                float kv = DEC_K(tid);
                zacc[tid] += 2.f * kv;
                ztmpT[tid] = zT[tid] + 0.5f * dt * kv;
            }
            __syncthreads();
            dec_eval(dw1, db1, dw2, db2, dw3, ztmpT, h1T, h2T, pd2, pd3, tid);
            if (tid < 256) {
                float kv = DEC_K(tid);
                zacc[tid] += 2.f * kv;
                ztmpT[tid] = zT[tid] + dt * kv;
            }
            __syncthreads();
            dec_eval(dw1, db1, dw2, db2, dw3, ztmpT, h1T, h2T, pd2, pd3, tid);
            if (tid < 256) {
                float kv = DEC_K(tid);
                zT[tid] += dt * (1.f / 6.f) * (zacc[tid] + kv);
            }
            __syncthreads();
        }

        // output projection (K-split 2, 256 thr, 8-row)
        if (tid < 256) {
            int d = tid % DD, h = tid / DD;   // K=16 per half
            float a[8];
#pragma unroll
            for (int r = 0; r < 8; ++r) a[r] = 0.f;
#pragma unroll
            for (int k = h * 16; k < h * 16 + 16; ++k) {
                float w = ow[k * DD + d];
                float4 z0 = *(const float4*)(zT + k * 8);
                float4 z1 = *(const float4*)(zT + k * 8 + 4);
                a[0] += z0.x * w; a[1] += z0.y * w; a[2] += z0.z * w; a[3] += z0.w * w;
                a[4] += z1.x * w; a[5] += z1.y * w; a[6] += z1.z * w; a[7] += z1.w * w;
            }
            float* p = pp + h * 1024 + d * 8;
            *(float4*)p       = make_float4(a[0], a[1], a[2], a[3]);
            *(float4*)(p + 4) = make_float4(a[4], a[5], a[6], a[7]);
        }
        __syncthreads();
        if (tid < DD) {
            int d = tid;
#pragma unroll
            for (int r = 0; r < 8; ++r)
                out[(size_t)(b0 + r) * (TT * DD) + (size_t)ti * DD + d] =
                    pp[d * 8 + r] + pp[1024 + d * 8 + r] + ob[d];
        }
        __syncthreads();
    }
}

extern "C" void kernel_launch(void* const* d_in, const int* in_sizes, int n_in,
                              void* d_out, int out_size) {
    (void)in_sizes; (void)n_in; (void)out_size;
    size_t smem = (size_t)SM_FLOATS * sizeof(float);
    cudaFuncSetAttribute(latent_ode_main, cudaFuncAttributeMaxDynamicSharedMemorySize, (int)smem);

    colsum_kernel<<<3, GU>>>((const float*)d_in[8], (const float*)d_in[12], (const float*)d_in[16]);

    latent_ode_main<<<NBLK, NTHR, smem>>>(
        (const float*)d_in[0], (const float*)d_in[1], (const int*)d_in[2], (const float*)d_in[3],
        (const float*)d_in[4],  (const float*)d_in[5],  (const float*)d_in[6],  (const float*)d_in[7],
        (const float*)d_in[8],  (const float*)d_in[9],  (const float*)d_in[10], (const float*)d_in[11],
        (const float*)d_in[12], (const float*)d_in[13], (const float*)d_in[14], (const float*)d_in[15],
        (const float*)d_in[16], (const float*)d_in[17], (const float*)d_in[18], (const float*)d_in[19],
        (const float*)d_in[20], (const float*)d_in[21], (const float*)d_in[22], (const float*)d_in[23],
        (const float*)d_in[24], (const float*)d_in[25], (const float*)d_in[26], (const float*)d_in[27],
        (const float*)d_in[28], (const float*)d_in[29], (const float*)d_in[30], (const float*)d_in[31],
        (float*)d_out);
}

// round 7
// speedup vs baseline: 1.0447x; 1.0005x over previous
#include <cuda_runtime.h>
#include <math.h>

#define TT   200
#define BB   1024
#define DD   128
#define TOBS 140
#define LL   20
#define LATD 32
#define GU   200
#define UNI  100
#define GIN  168      /* effective K: y(40)+x(128); ones-row folded into colsum */
#define ROWS 8
#define NTHR 512
#define NBLK (BB / ROWS)

#define KH   84       /* K per half for GRU l1 split-2 */

#define SM_FLOATS 51208

__device__ float g_colsum[3 * GU];

// branchless fast tanh: clamp + EX2-based exp + fast divide (~8 instr)
__device__ __forceinline__ float fast_tanh(float x) {
    float xc = fminf(fmaxf(x, -9.f), 9.f);
    float e = __expf(2.f * xc);
    return __fdividef(e - 1.f, e + 1.f);
}
__device__ __forceinline__ float fast_sigmoid(float x) {
    return __fdividef(1.f, 1.f + __expf(-x));
}

__global__ void colsum_kernel(const float* __restrict__ uw1,
                              const float* __restrict__ rw1,
                              const float* __restrict__ nw1) {
    int j = threadIdx.x;
    const float* w = (blockIdx.x == 0) ? uw1 : (blockIdx.x == 1 ? rw1 : nw1);
    float sacc = 0.f;
    for (int k = GIN; k < 2 * LL + 2 * DD; ++k) sacc += w[k * GU + j];
    g_colsum[blockIdx.x * GU + j] = sacc;
}

// ---- GRU layer1, dual gate (u,r), K-split half, pipelined weight prefetch ----
__device__ __forceinline__ void gru_l1_dual_ks(const float* __restrict__ wA,
                                               const float* __restrict__ wB,
                                               const float* __restrict__ ycT,
                                               float* __restrict__ pU,
                                               float* __restrict__ pR,
                                               int j, int ks) {
    float aA[8], aB[8];
#pragma unroll
    for (int r = 0; r < 8; ++r) { aA[r] = 0.f; aB[r] = 0.f; }
    const float* pA = wA + (size_t)ks * KH * GU + j;
    const float* pB = wB + (size_t)ks * KH * GU + j;
    const float* yc = ycT + ks * KH * 8;
    float wa[6], wb[6];
#pragma unroll
    for (int kk = 0; kk < 6; ++kk) { wa[kk] = pA[kk * GU]; wb[kk] = pB[kk * GU]; }
#pragma unroll 1
    for (int t = 0; t < 14; ++t) {
        float na[6], nb[6];
        if (t + 1 < 14) {
#pragma unroll
            for (int kk = 0; kk < 6; ++kk) {
                na[kk] = pA[((t + 1) * 6 + kk) * GU];
                nb[kk] = pB[((t + 1) * 6 + kk) * GU];
            }
        }
#pragma unroll
        for (int kk = 0; kk < 6; ++kk) {
            int k = t * 6 + kk;
            float4 y0 = *(const float4*)(yc + k * 8);
            float4 y1 = *(const float4*)(yc + k * 8 + 4);
            float w0 = wa[kk], w1 = wb[kk];
            aA[0] += y0.x * w0; aA[1] += y0.y * w0; aA[2] += y0.z * w0; aA[3] += y0.w * w0;
            aA[4] += y1.x * w0; aA[5] += y1.y * w0; aA[6] += y1.z * w0; aA[7] += y1.w * w0;
            aB[0] += y0.x * w1; aB[1] += y0.y * w1; aB[2] += y0.z * w1; aB[3] += y0.w * w1;
            aB[4] += y1.x * w1; aB[5] += y1.y * w1; aB[6] += y1.z * w1; aB[7] += y1.w * w1;
        }
        if (t + 1 < 14) {
#pragma unroll
            for (int kk = 0; kk < 6; ++kk) { wa[kk] = na[kk]; wb[kk] = nb[kk]; }
        }
    }
    float* u = pU + ks * 1600 + j * 8;
    float* rr = pR + ks * 1600 + j * 8;
    *(float4*)u        = make_float4(aA[0], aA[1], aA[2], aA[3]);
    *(float4*)(u + 4)  = make_float4(aA[4], aA[5], aA[6], aA[7]);
    *(float4*)rr       = make_float4(aB[0], aB[1], aB[2], aB[3]);
    *(float4*)(rr + 4) = make_float4(aB[4], aB[5], aB[6], aB[7]);
}

__device__ __forceinline__ void gru_l1_single_ks(const float* __restrict__ wA,
                                                 const float* __restrict__ ycT,
                                                 float* __restrict__ pN,
                                                 int j, int ks) {
    float aA[8];
#pragma unroll
    for (int r = 0; r < 8; ++r) aA[r] = 0.f;
    const float* pA = wA + (size_t)ks * KH * GU + j;
    const float* yc = ycT + ks * KH * 8;
    float wa[12];
#pragma unroll
    for (int kk = 0; kk < 12; ++kk) wa[kk] = pA[kk * GU];
#pragma unroll 1
    for (int t = 0; t < 7; ++t) {
        float na[12];
        if (t + 1 < 7) {
#pragma unroll
            for (int kk = 0; kk < 12; ++kk) na[kk] = pA[((t + 1) * 12 + kk) * GU];
        }
#pragma unroll
        for (int kk = 0; kk < 12; ++kk) {
            int k = t * 12 + kk;
            float4 y0 = *(const float4*)(yc + k * 8);
            float4 y1 = *(const float4*)(yc + k * 8 + 4);
            float w0 = wa[kk];
            aA[0] += y0.x * w0; aA[1] += y0.y * w0; aA[2] += y0.z * w0; aA[3] += y0.w * w0;
            aA[4] += y1.x * w0; aA[5] += y1.y * w0; aA[6] += y1.z * w0; aA[7] += y1.w * w0;
        }
        if (t + 1 < 7) {
#pragma unroll
            for (int kk = 0; kk < 12; ++kk) wa[kk] = na[kk];
        }
    }
    float* p = pN + ks * 1600 + j * 8;
    *(float4*)p       = make_float4(aA[0], aA[1], aA[2], aA[3]);
    *(float4*)(p + 4) = make_float4(aA[4], aA[5], aA[6], aA[7]);
}

// encoder MLP: l1 direct (400 thr, 2 rows, no reduce), l2 partials (200 thr)
__device__ __forceinline__ void enc_eval(const float* __restrict__ ew1,
                                         const float* __restrict__ eb1,
                                         const float* __restrict__ ew2,
                                         const float* __restrict__ ytmpT,
                                         float* __restrict__ hencT,
                                         float* __restrict__ pe, int tid) {
    if (tid < 400) {
        int j = tid % UNI, rq = tid / UNI;   // rows 2rq, 2rq+1
        float a0 = eb1[j], a1 = a0;
#pragma unroll
        for (int k = 0; k < LL; ++k) {
            float w = ew1[k * UNI + j];
            float2 yv = *(const float2*)(ytmpT + k * 8 + 2 * rq);
            a0 += yv.x * w; a1 += yv.y * w;
        }
        *(float2*)(hencT + j * 8 + 2 * rq) = make_float2(fast_tanh(a0), fast_tanh(a1));
    }
    __syncthreads();
    if (tid < 200) {
        int jj = tid % LL, ks = tid / LL;   // ks 0..9, K=10
        float a[8];
#pragma unroll
        for (int r = 0; r < 8; ++r) a[r] = 0.f;
#pragma unroll
        for (int k = ks * 10; k < ks * 10 + 10; ++k) {
            float w = ew2[k * LL + jj];
            float4 y0 = *(const float4*)(hencT + k * 8);
            float4 y1 = *(const float4*)(hencT + k * 8 + 4);
            a[0] += y0.x * w; a[1] += y0.y * w; a[2] += y0.z * w; a[3] += y0.w * w;
            a[4] += y1.x * w; a[5] += y1.y * w; a[6] += y1.z * w; a[7] += y1.w * w;
        }
        float* p = pe + ks * 160 + jj * 8;
        *(float4*)p       = make_float4(a[0], a[1], a[2], a[3]);
        *(float4*)(p + 4) = make_float4(a[4], a[5], a[6], a[7]);
    }
    __syncthreads();
}

#define ENC_K(tidv) (pe[(tidv)] + pe[160 + (tidv)] + pe[320 + (tidv)] + pe[480 + (tidv)] + \
                     pe[640 + (tidv)] + pe[800 + (tidv)] + pe[960 + (tidv)] + pe[1120 + (tidv)] + \
                     pe[1280 + (tidv)] + pe[1440 + (tidv)] + eb2[(tidv) >> 3])

// decoder MLP: l1 direct; l2 K-split 4 (8-row); l3 K-split 10 (8-row)
__device__ __forceinline__ void dec_eval(const float* __restrict__ dw1,
                                         const float* __restrict__ db1,
                                         const float* __restrict__ dw2,
                                         const float* __restrict__ db2,
                                         const float* __restrict__ dw3,
                                         const float* __restrict__ zin,
                                         float* __restrict__ h1T,
                                         float* __restrict__ h2T,
                                         float* __restrict__ pd2,
                                         float* __restrict__ pd3, int tid) {
    if (tid < 400) {
        int j = tid % UNI, rq = tid / UNI;
        float a0 = db1[j], a1 = a0;
#pragma unroll 8
        for (int k = 0; k < LATD; ++k) {
            float w = dw1[k * UNI + j];
            float2 zv = *(const float2*)(zin + k * 8 + 2 * rq);
            a0 += zv.x * w; a1 += zv.y * w;
        }
        *(float2*)(h1T + j * 8 + 2 * rq) = make_float2(fast_tanh(a0), fast_tanh(a1));
    }
    __syncthreads();
    if (tid < 400) {
        int j = tid % UNI, ks = tid / UNI;   // ks 0..3, K=25
        float a[8];
#pragma unroll
        for (int r = 0; r < 8; ++r) a[r] = 0.f;
#pragma unroll 5
        for (int k = ks * 25; k < ks * 25 + 25; ++k) {
            float w = dw2[k * UNI + j];
            float4 z0 = *(const float4*)(h1T + k * 8);
            float4 z1 = *(const float4*)(h1T + k * 8 + 4);
            a[0] += z0.x * w; a[1] += z0.y * w; a[2] += z0.z * w; a[3] += z0.w * w;
            a[4] += z1.x * w; a[5] += z1.y * w; a[6] += z1.z * w; a[7] += z1.w * w;
        }
        float* p = pd2 + ks * 800 + j * 8;
        *(float4*)p       = make_float4(a[0], a[1], a[2], a[3]);
        *(float4*)(p + 4) = make_float4(a[4], a[5], a[6], a[7]);
    }
    __syncthreads();
    for (int i = tid; i < 800; i += NTHR)
        h2T[i] = fast_tanh(pd2[i] + pd2[800 + i] + pd2[1600 + i] + pd2[2400 + i] + db2[i >> 3]);
    __syncthreads();
    if (tid < 320) {
        int jj = tid % LATD, ks = tid / LATD;  // ks 0..9, K=10
        float a[8];
#pragma unroll
        for (int r = 0; r < 8; ++r) a[r] = 0.f;
#pragma unroll
        for (int k = ks * 10; k < ks * 10 + 10; ++k) {
            float w = dw3[k * LATD + jj];
            float4 z0 = *(const float4*)(h2T + k * 8);
            float4 z1 = *(const float4*)(h2T + k * 8 + 4);
            a[0] += z0.x * w; a[1] += z0.y * w; a[2] += z0.z * w; a[3] += z0.w * w;
            a[4] += z1.x * w; a[5] += z1.y * w; a[6] += z1.z * w; a[7] += z1.w * w;
        }
        float* p = pd3 + ks * 256 + jj * 8;
        *(float4*)p       = make_float4(a[0], a[1], a[2], a[3]);
        *(float4*)(p + 4) = make_float4(a[4], a[5], a[6], a[7]);
    }
    __syncthreads();
}

#define DEC_K(tidv) (pd3[(tidv)] + pd3[256 + (tidv)] + pd3[512 + (tidv)] + pd3[768 + (tidv)] + \
                     pd3[1024 + (tidv)] + pd3[1280 + (tidv)] + pd3[1536 + (tidv)] + pd3[1792 + (tidv)] + \
                     pd3[2048 + (tidv)] + pd3[2304 + (tidv)] + db3[(tidv) >> 3])

extern "C" __global__ void __launch_bounds__(NTHR, 1)
latent_ode_main(const float* __restrict__ truth, const float* __restrict__ tarr,
                const int* __restrict__ obs_idx, const float* __restrict__ eps,
                const float* __restrict__ ew1g, const float* __restrict__ eb1g,
                const float* __restrict__ ew2g, const float* __restrict__ eb2g,
                const float* __restrict__ uw1, const float* __restrict__ ub1g,
                const float* __restrict__ uw2g, const float* __restrict__ ub2g,
                const float* __restrict__ rw1, const float* __restrict__ rb1g,
                const float* __restrict__ rw2g, const float* __restrict__ rb2g,
                const float* __restrict__ nw1, const float* __restrict__ nb1g,
                const float* __restrict__ nw2g, const float* __restrict__ nb2g,
                const float* __restrict__ z0w1, const float* __restrict__ z0b1,
                const float* __restrict__ z0w2, const float* __restrict__ z0b2,
                const float* __restrict__ dw1g, const float* __restrict__ db1g,
                const float* __restrict__ dw2g, const float* __restrict__ db2g,
                const float* __restrict__ dw3g, const float* __restrict__ db3g,
                const float* __restrict__ owg, const float* __restrict__ obg,
                float* __restrict__ out) {
    extern __shared__ float s[];
    const int tid = threadIdx.x;
    const int b0 = blockIdx.x * ROWS;

    float* zT = s;           // [32][8] k-major, persistent
    float* P  = s + 256;

    // ---------------- encoder smem layout ----------------
    float* ew1   = P;            // 2000
    float* ew2   = P + 2000;     // 2000
    float* eb1   = P + 4000;     // 100
    float* eb2   = P + 4100;     // 20 (pad to 4128)
    float* uw2   = P + 4128;     // 8000
    float* rw2   = P + 12128;    // 8000
    float* nw2   = P + 20128;    // 8000
    float* ub1   = P + 28128;    // 200
    float* rb1   = P + 28328;    // 200
    float* nb1   = P + 28528;    // 200
    float* ub2   = P + 28728;    // 40
    float* rb2   = P + 28768;    // 40
    float* nb2   = P + 28808;    // 40
    float* csu   = P + 28848;    // 200
    float* csr   = P + 29048;    // 200
    float* csn   = P + 29248;    // 200
    float* y     = P + 29448;    // 320  [8][40]
    float* ycT   = P + 29768;    // 1344 [168][8]
    float* ytmpT = P + 31112;    // 160
    float* accT  = P + 31272;    // 160
    float* hencT = P + 31432;    // 800
    float* pe    = P + 33832;    // 1600 [10][20][8]
    float* hTa   = P + 35432;    // 1600 [200][8]
    float* hTb   = P + 37032;    // 1600
    float* pL1   = P + 38632;    // 6400 [2 gates][2 ks][200][8]
    float* p2    = P + 45032;    // 2560 [2][4][40][8]
    float* pn    = P + 47592;    // 2560 [8][40][8]
    float* u_    = P + 50152;    // 320  [8][40]
    float* dts   = P + 50472;    // 140
    float* iob   = P + 50612;    // 140 (ints as bits)
    float* ddt   = P + 50752;    // 200 (outside decoder alias region -> persists)

    for (int i = tid; i < 2000; i += NTHR) { ew1[i] = ew1g[i]; ew2[i] = ew2g[i]; }
    for (int i = tid; i < 100;  i += NTHR) eb1[i] = eb1g[i];
    for (int i = tid; i < 20;   i += NTHR) eb2[i] = eb2g[i];
    for (int i = tid; i < 8000; i += NTHR) { uw2[i] = uw2g[i]; rw2[i] = rw2g[i]; nw2[i] = nw2g[i]; }
    for (int i = tid; i < 200;  i += NTHR) {
        ub1[i] = ub1g[i]; rb1[i] = rb1g[i]; nb1[i] = nb1g[i];
        csu[i] = g_colsum[i]; csr[i] = g_colsum[200 + i]; csn[i] = g_colsum[400 + i];
    }
    for (int i = tid; i < 40; i += NTHR) { ub2[i] = ub2g[i]; rb2[i] = rb2g[i]; nb2[i] = nb2g[i]; }
    for (int i = tid; i < ROWS * 40; i += NTHR) y[i] = 0.f;
    for (int i = tid; i < TOBS; i += NTHR) {
        int io = obs_idx[TOBS - 1 - i];
        iob[i] = __int_as_float(io);
        dts[i] = (i > 0) ? (tarr[io] - tarr[obs_idx[TOBS - i]]) : 0.f;
    }
    for (int i = tid; i < TT - 1; i += NTHR) ddt[i] = tarr[i + 1] - tarr[i];
    __syncthreads();

    // ================= encoder scan =================
    for (int st = 0; st < TOBS; ++st) {
        int io = __float_as_int(iob[st]);
        float dt = dts[st];

        // ---- RK4 on ym ----
        if (tid < 160) { int j = tid >> 3, r = tid & 7; ytmpT[tid] = y[r * 40 + j]; }
        __syncthreads();
        enc_eval(ew1, eb1, ew2, ytmpT, hencT, pe, tid);
        if (tid < 160) {
            int j = tid >> 3, r = tid & 7;
            float kv = ENC_K(tid);
            accT[tid] = kv;
            ytmpT[tid] = y[r * 40 + j] + 0.5f * dt * kv;
        }
        __syncthreads();
        enc_eval(ew1, eb1, ew2, ytmpT, hencT, pe, tid);
        if (tid < 160) {
            int j = tid >> 3, r = tid & 7;
            float kv = ENC_K(tid);
            accT[tid] += 2.f * kv;
            ytmpT[tid] = y[r * 40 + j] + 0.5f * dt * kv;
        }
        __syncthreads();
        enc_eval(ew1, eb1, ew2, ytmpT, hencT, pe, tid);
        if (tid < 160) {
            int j = tid >> 3, r = tid & 7;
            float kv = ENC_K(tid);
            accT[tid] += 2.f * kv;
            ytmpT[tid] = y[r * 40 + j] + dt * kv;
        }
        __syncthreads();
        enc_eval(ew1, eb1, ew2, ytmpT, hencT, pe, tid);
        if (tid < 160) {
            int j = tid >> 3, r = tid & 7;
            float kv = ENC_K(tid);
            y[r * 40 + j] += dt * (1.f / 6.f) * (accT[tid] + kv);
        }
        __syncthreads();

        // ---- build ycT ----
        for (int i = tid; i < GIN * ROWS; i += NTHR) {
            int k = i >> 3, r = i & 7;
            ycT[i] = (k < 40) ? y[r * 40 + k]
                              : truth[(size_t)io * (BB * DD) + (size_t)(b0 + r) * DD + (k - 40)];
        }
        __syncthreads();

        // ---- u,r layer1 (K-split 2, 400 thr) ----
        if (tid < 400)
            gru_l1_dual_ks(uw1, rw1, ycT, pL1, pL1 + 3200, tid % GU, tid / GU);
        __syncthreads();
        // reduce + bias + tanh
        for (int i = tid; i < 3200; i += NTHR) {
            int g = i / 1600, rem = i % 1600, j = rem >> 3;
            float base = g ? (csr[j] + rb1[j]) : (csu[j] + ub1[j]);
            float v = pL1[g * 3200 + rem] + pL1[g * 3200 + 1600 + rem] + base;
            (g ? hTb : hTa)[rem] = fast_tanh(v);
        }
        __syncthreads();

        // ---- u,r layer2 (K-split 4, 320 thr) ----
        if (tid < 320) {
            int g = tid / 160, rem = tid % 160, jj = rem % 40, ks = rem / 40;  // K=50
            const float* hT = g ? hTb : hTa;
            const float* w2 = g ? rw2 : uw2;
            float a[8];
#pragma unroll
            for (int r = 0; r < 8; ++r) a[r] = 0.f;
#pragma unroll 10
            for (int k = ks * 50; k < ks * 50 + 50; ++k) {
                float w = w2[k * 40 + jj];
                float4 h0 = *(const float4*)(hT + k * 8);
                float4 h1 = *(const float4*)(hT + k * 8 + 4);
                a[0] += h0.x * w; a[1] += h0.y * w; a[2] += h0.z * w; a[3] += h0.w * w;
                a[4] += h1.x * w; a[5] += h1.y * w; a[6] += h1.z * w; a[7] += h1.w * w;
            }
            float* p = p2 + g * 1280 + ks * 320 + jj * 8;
            *(float4*)p       = make_float4(a[0], a[1], a[2], a[3]);
            *(float4*)(p + 4) = make_float4(a[4], a[5], a[6], a[7]);
        }
        __syncthreads();
        // reduce + sigmoid; g==1 (r gate) scales ycT in place, g==0 stores u_
        for (int i = tid; i < 640; i += NTHR) {
            int g = i / 320, rem = i % 320, jj = rem >> 3, r = rem & 7;
            const float* p = p2 + g * 1280;
            float a = p[rem] + p[320 + rem] + p[640 + rem] + p[960 + rem] + (g ? rb2 : ub2)[jj];
            float sg = fast_sigmoid(a);
            if (g) ycT[jj * 8 + r] *= sg;   // rem == jj*8+r, jj<40: y-part of ycT
            else   u_[r * 40 + jj] = sg;
        }
        __syncthreads();

        // ---- n layer1 (K-split 2, 400 thr; ycT already r-scaled) ----
        if (tid < 400)
            gru_l1_single_ks(nw1, ycT, pL1, tid % GU, tid / GU);
        __syncthreads();
        for (int i = tid; i < 1600; i += NTHR) {
            int j = i >> 3;
            hTa[i] = fast_tanh(pL1[i] + pL1[1600 + i] + csn[j] + nb1[j]);
        }
        __syncthreads();

        // ---- n layer2 (K-split 8, 320 thr) ----
        if (tid < 320) {
            int jj = tid % 40, ks = tid / 40;   // K=25
            float a[8];
#pragma unroll
            for (int r = 0; r < 8; ++r) a[r] = 0.f;
#pragma unroll 5
            for (int k = ks * 25; k < ks * 25 + 25; ++k) {
                float w = nw2[k * 40 + jj];
                float4 h0 = *(const float4*)(hTa + k * 8);
                float4 h1 = *(const float4*)(hTa + k * 8 + 4);
                a[0] += h0.x * w; a[1] += h0.y * w; a[2] += h0.z * w; a[3] += h0.w * w;
                a[4] += h1.x * w; a[5] += h1.y * w; a[6] += h1.z * w; a[7] += h1.w * w;
            }
            float* p = pn + ks * 320 + jj * 8;
            *(float4*)p       = make_float4(a[0], a[1], a[2], a[3]);
            *(float4*)(p + 4) = make_float4(a[4], a[5], a[6], a[7]);
        }
        __syncthreads();
        // reduce + state update
        if (tid < 320) {
            int jj = tid >> 3, r = tid & 7;
            float a = pn[tid] + pn[320 + tid] + pn[640 + tid] + pn[960 + tid]
                    + pn[1280 + tid] + pn[1600 + tid] + pn[1920 + tid] + pn[2240 + tid] + nb2[jj];
            float val = (jj < LL) ? a : fabsf(a);
            float uu = u_[r * 40 + jj];
            y[r * 40 + jj] = (1.f - uu) * val + uu * y[r * 40 + jj];
        }
        __syncthreads();
    }

    // ================= z0 head (once) =================
    for (int i = tid; i < ROWS * UNI; i += NTHR) {
        int r = i / UNI, j = i % UNI;
        float a = z0b1[j];
#pragma unroll 4
        for (int k = 0; k < 40; ++k) a += y[r * 40 + k] * z0w1[k * UNI + j];
        hencT[i] = fast_tanh(a);
    }
    __syncthreads();
    for (int i = tid; i < ROWS * 64; i += NTHR) {
        int r = i / 64, j = i % 64;
        float a = z0b2[j];
#pragma unroll 4
        for (int k = 0; k < UNI; ++k) a += hencT[r * UNI + k] * z0w2[k * 64 + j];
        hTa[r * 64 + j] = a;
    }
    __syncthreads();
    if (tid < 256) {
        int r = tid >> 5, j = tid & 31;
        float m = hTa[r * 64 + j];
        float sd = fabsf(hTa[r * 64 + 32 + j]);
        zT[j * 8 + r] = m + eps[(size_t)(b0 + r) * LATD + j] * sd;
    }
    __syncthreads();

    // ---------------- decoder smem layout (aliases P; ddt beyond -> safe) ----------------
    float* dw1   = P;             // 3200
    float* dw2   = P + 3200;      // 10000
    float* dw3   = P + 13200;     // 3200
    float* db1   = P + 16400;     // 100
    float* db2   = P + 16500;     // 100
    float* db3   = P + 16600;     // 32
    float* ow    = P + 16632;     // 4096
    float* ob    = P + 20728;     // 128
    float* h1T   = P + 20856;     // 800
    float* h2T   = P + 21656;     // 800
    float* ztmpT = P + 22456;     // 256
    float* zacc  = P + 22712;     // 256
    float* pd2   = P + 22968;     // 3200 [4][100][8]
    float* pd3   = P + 26168;     // 2560 [10][32][8]
    float* pp    = P + 28728;     // 2048 [2][128][8]

    for (int i = tid; i < 3200;  i += NTHR) { dw1[i] = dw1g[i]; dw3[i] = dw3g[i]; }
    for (int i = tid; i < 10000; i += NTHR) dw2[i] = dw2g[i];
    for (int i = tid; i < 100;   i += NTHR) { db1[i] = db1g[i]; db2[i] = db2g[i]; }
    for (int i = tid; i < 32;    i += NTHR) db3[i] = db3g[i];
    for (int i = tid; i < 4096;  i += NTHR) ow[i] = owg[i];
    for (int i = tid; i < 128;   i += NTHR) ob[i] = obg[i];
    __syncthreads();

    // ================= decoder scan + projection =================
    for (int ti = 0; ti < TT; ++ti) {
        if (ti > 0) {
            float dt = ddt[ti - 1];
            if (tid < 256) ztmpT[tid] = zT[tid];
            __syncthreads();
            dec_eval(dw1, db1, dw2, db2, dw3, ztmpT, h1T, h2T, pd2, pd3, tid);
            if (tid < 256) {
                float kv = DEC_K(tid);
                zacc[tid] = kv;
                ztmpT[tid] = zT[tid] + 0.5f * dt * kv;
            }
            __syncthreads();
            dec_eval(dw1, db1, dw2, db2, dw3, ztmpT, h1T, h2T, pd2, pd3, tid);
            if (tid < 256) {
                float kv = DEC_K(tid);
                zacc[tid] += 2.f * kv;
                ztmpT[tid] = zT[tid] + 0.5f * dt * kv;
            }
            __syncthreads();
            dec_eval(dw1, db1, dw2, db2, dw3, ztmpT, h1T, h2T, pd2, pd3, tid);
            if (tid < 256) {
                float kv = DEC_K(tid);
                zacc[tid] += 2.f * kv;
                ztmpT[tid] = zT[tid] + dt * kv;
            }
            __syncthreads();
            dec_eval(dw1, db1, dw2, db2, dw3, ztmpT, h1T, h2T, pd2, pd3, tid);
            if (tid < 256) {
                float kv = DEC_K(tid);
                zT[tid] += dt * (1.f / 6.f) * (zacc[tid] + kv);
            }
            __syncthreads();
        }

        // output projection (K-split 2, 256 thr, 8-row)
        if (tid < 256) {
            int d = tid % DD, h = tid / DD;   // K=16 per half
            float a[8];
#pragma unroll
            for (int r = 0; r < 8; ++r) a[r] = 0.f;
#pragma unroll
            for (int k = h * 16; k < h * 16 + 16; ++k) {
                float w = ow[k * DD + d];
                float4 z0 = *(const float4*)(zT + k * 8);
                float4 z1 = *(const float4*)(zT + k * 8 + 4);
                a[0] += z0.x * w; a[1] += z0.y * w; a[2] += z0.z * w; a[3] += z0.w * w;
                a[4] += z1.x * w; a[5] += z1.y * w; a[6] += z1.z * w; a[7] += z1.w * w;
            }
            float* p = pp + h * 1024 + d * 8;
            *(float4*)p       = make_float4(a[0], a[1], a[2], a[3]);
            *(float4*)(p + 4) = make_float4(a[4], a[5], a[6], a[7]);
        }
        __syncthreads();
        if (tid < DD) {
            int d = tid;
#pragma unroll
            for (int r = 0; r < 8; ++r)
                out[(size_t)(b0 + r) * (TT * DD) + (size_t)ti * DD + d] =
                    pp[d * 8 + r] + pp[1024 + d * 8 + r] + ob[d];
        }
        __syncthreads();
    }
}

extern "C" void kernel_launch(void* const* d_in, const int* in_sizes, int n_in,
                              void* d_out, int out_size) {
    (void)in_sizes; (void)n_in; (void)out_size;
    size_t smem = (size_t)SM_FLOATS * sizeof(float);
    cudaFuncSetAttribute(latent_ode_main, cudaFuncAttributeMaxDynamicSharedMemorySize, (int)smem);

    colsum_kernel<<<3, GU>>>((const float*)d_in[8], (const float*)d_in[12], (const float*)d_in[16]);

    latent_ode_main<<<NBLK, NTHR, smem>>>(
        (const float*)d_in[0], (const float*)d_in[1], (const int*)d_in[2], (const float*)d_in[3],
        (const float*)d_in[4],  (const float*)d_in[5],  (const float*)d_in[6],  (const float*)d_in[7],
        (const float*)d_in[8],  (const float*)d_in[9],  (const float*)d_in[10], (const float*)d_in[11],
        (const float*)d_in[12], (const float*)d_in[13], (const float*)d_in[14], (const float*)d_in[15],
        (const float*)d_in[16], (const float*)d_in[17], (const float*)d_in[18], (const float*)d_in[19],
        (const float*)d_in[20], (const float*)d_in[21], (const float*)d_in[22], (const float*)d_in[23],
        (const float*)d_in[24], (const float*)d_in[25], (const float*)d_in[26], (const float*)d_in[27],
        (const float*)d_in[28], (const float*)d_in[29], (const float*)d_in[30], (const float*)d_in[31],
        (float*)d_out);
}